// round 11
// baseline (speedup 1.0000x reference)
#include <cuda_runtime.h>

namespace {

constexpr int T  = 4096;
constexpr int H  = 16;
constexpr int P  = 64;    // d_head
constexpr int N  = 128;   // d_state
constexpr int L  = 64;    // block_len (last chunk)
constexpr int T0 = T - L; // 4032
constexpr int NT = 16;    // n-columns per block

__device__ __forceinline__ void fma2(unsigned long long& d,
                                     unsigned long long a,
                                     unsigned long long b) {
    asm("fma.rn.f32x2 %0, %1, %2, %0;" : "+l"(d) : "l"(a), "l"(b));
}

__global__ __launch_bounds__(128, 2)
void mamba_final_state_kernel(const float* __restrict__ X,
                              const float* __restrict__ A,
                              const float* __restrict__ Bm,
                              float* __restrict__ out) {
    const int bh    = blockIdx.x;      // 0..31  (b*16 + h)
    const int b     = bh >> 4;
    const int h     = bh & 15;
    const int ntile = blockIdx.y;      // 0..7, 16 n-columns each
    const int tid   = threadIdx.x;     // 128 threads

    const int lane  = tid & 31;

    __shared__ float Xs[L][P];         // 16 KB, raw X
    __shared__ float Bs[L][NT];        // 4 KB, later scaled by w[l]
    __shared__ float wpart[L];
    __shared__ float wtot[2];
    __shared__ float wsh[L];

    // ---- issue ALL gmem loads up front (independent) ----

    // A for last chunk -> registers of threads 0..63
    float a = 0.f;
    if (tid < L)
        a = A[(size_t)(b * T + T0 + tid) * H + h];

    // X tile raw: 64x64 = 1024 float4, 8 per thread
    {
        const float* xbase = X + (size_t)(b * T + T0) * (H * P) + (size_t)h * P;
        #pragma unroll
        for (int it = 0; it < 8; it++) {
            int i  = tid + it * 128;   // 0..1023
            int l  = i >> 4;           // 16 float4 per row
            int c4 = i & 15;
            float4 v = *reinterpret_cast<const float4*>(
                xbase + (size_t)l * (H * P) + c4 * 4);
            *reinterpret_cast<float4*>(&Xs[l][c4 * 4]) = v;
        }
    }

    // B tile raw: 64x16 = 256 float4, 2 per thread
    {
        const float* bbase = Bm + (size_t)(b * T + T0) * (H * N)
                                + (size_t)h * N + ntile * NT;
        #pragma unroll
        for (int it = 0; it < 2; it++) {
            int i  = tid + it * 128;   // 0..255
            int l  = i >> 2;           // 4 float4 per row
            int c4 = i & 3;
            float4 v = *reinterpret_cast<const float4*>(
                bbase + (size_t)l * (H * N) + c4 * 4);
            *reinterpret_cast<float4*>(&Bs[l][c4 * 4]) = v;
        }
    }

    // ---- warp-shfl inclusive scan of A (overlaps the loads) ----
    if (tid < L) {
        float c = a;
        #pragma unroll
        for (int off = 1; off < 32; off <<= 1) {
            float t = __shfl_up_sync(0xffffffffu, c, off);
            if (lane >= off) c += t;
        }
        wpart[tid] = c;
        if (lane == 31) wtot[tid >> 5] = c;
    }
    __syncthreads();

    // ---- w[l] = exp(2*S - cumsum_incl[l]) ----
    if (tid < L) {
        float tot0 = wtot[0];
        float S    = tot0 + wtot[1];
        float cc   = wpart[tid] + (tid >= 32 ? tot0 : 0.f);
        wsh[tid]   = __expf(2.f * S - cc);
    }
    __syncthreads();

    // ---- fold w into B rows in place (256 float4) ----
    {
        #pragma unroll
        for (int it = 0; it < 2; it++) {
            int i   = tid + it * 128;
            int l   = i >> 2;
            int c4  = i & 3;
            float wl = wsh[l];
            float4 v = *reinterpret_cast<float4*>(&Bs[l][c4 * 4]);
            v.x *= wl; v.y *= wl; v.z *= wl; v.w *= wl;
            *reinterpret_cast<float4*>(&Bs[l][c4 * 4]) = v;
        }
    }
    __syncthreads();

    // ---- compute: thread -> (p, 8 consecutive n); packed f32x2 FMA ----
    const int p  = tid & 63;
    const int ng = tid >> 6;           // 0..1

    unsigned long long acc0 = 0ull, acc1 = 0ull, acc2 = 0ull, acc3 = 0ull;

    #pragma unroll
    for (int l = 0; l < L; l++) {
        float xv = Xs[l][p];                          // conflict-free LDS
        unsigned long long x2;
        asm("mov.b64 %0, {%1, %1};" : "=l"(x2) : "f"(xv));
        const ulonglong2* bp =
            reinterpret_cast<const ulonglong2*>(&Bs[l][ng * 8]);  // 32B aligned
        ulonglong2 q0 = bp[0];                        // LDS.128 broadcast
        ulonglong2 q1 = bp[1];                        // LDS.128 broadcast
        fma2(acc0, x2, q0.x);
        fma2(acc1, x2, q0.y);
        fma2(acc2, x2, q1.x);
        fma2(acc3, x2, q1.y);
    }

    float* o = out + ((size_t)(bh * P + p)) * N + ntile * NT + ng * 8;
    ulonglong2 s0; s0.x = acc0; s0.y = acc1;
    ulonglong2 s1; s1.x = acc2; s1.y = acc3;
    *reinterpret_cast<ulonglong2*>(o)     = s0;       // STG.128
    *reinterpret_cast<ulonglong2*>(o + 4) = s1;       // STG.128
}

} // namespace

extern "C" void kernel_launch(void* const* d_in, const int* in_sizes, int n_in,
                              void* d_out, int out_size) {
    const float* X = (const float*)d_in[0];  // (2, 4096, 16, 64)  f32
    const float* A = (const float*)d_in[1];  // (2, 4096, 16)      f32
    const float* B = (const float*)d_in[2];  // (2, 4096, 16, 128) f32
    float* out = (float*)d_out;              // (2, 16, 64, 128)   f32

    dim3 grid(32, 8);   // (b*h pairs, n-tiles of 16)
    mamba_final_state_kernel<<<grid, 128>>>(X, A, B, out);
}

// round 12
// speedup vs baseline: 1.0268x; 1.0268x over previous
#include <cuda_runtime.h>

namespace {

constexpr int T  = 4096;
constexpr int H  = 16;
constexpr int P  = 64;    // d_head
constexpr int N  = 128;   // d_state
constexpr int L  = 64;    // block_len (last chunk)
constexpr int T0 = T - L; // 4032

__device__ __forceinline__ void fma2(unsigned long long& d,
                                     unsigned long long a,
                                     unsigned long long b) {
    asm("fma.rn.f32x2 %0, %1, %2, %0;" : "+l"(d) : "l"(a), "l"(b));
}

__global__ __launch_bounds__(256, 1)
void mamba_final_state_kernel(const float* __restrict__ X,
                              const float* __restrict__ A,
                              const float* __restrict__ Bm,
                              float* __restrict__ out) {
    const int bh    = blockIdx.x;      // 0..31  (b*16 + h)
    const int b     = bh >> 4;
    const int h     = bh & 15;
    const int ntile = blockIdx.y;      // 0..3, 32 n-columns each
    const int tid   = threadIdx.x;     // 256 threads

    const int lane  = tid & 31;

    __shared__ float Xs[L][P];         // 16 KB, raw X
    __shared__ float Bs[L][32];        // 8 KB, scaled by w[l] in fold pass
    __shared__ float wpart[L];         // inclusive-scan partials
    __shared__ float wtot[2];          // warp totals

    // ---- issue ALL gmem loads up front (no dependency between them) ----

    // A for last chunk -> registers of threads 0..63
    float a = 0.f;
    if (tid < L)
        a = A[(size_t)(b * T + T0 + tid) * H + h];

    // X tile raw: 64x64 = 1024 float4
    {
        const float* xbase = X + (size_t)(b * T + T0) * (H * P) + (size_t)h * P;
        #pragma unroll
        for (int it = 0; it < 4; it++) {
            int i  = tid + it * 256;   // 0..1023
            int l  = i >> 4;           // 16 float4 per row
            int c4 = i & 15;
            float4 v = *reinterpret_cast<const float4*>(
                xbase + (size_t)l * (H * P) + c4 * 4);
            *reinterpret_cast<float4*>(&Xs[l][c4 * 4]) = v;
        }
    }

    // B tile raw: 64x32 = 512 float4
    {
        const float* bbase = Bm + (size_t)(b * T + T0) * (H * N)
                                + (size_t)h * N + ntile * 32;
        #pragma unroll
        for (int it = 0; it < 2; it++) {
            int i  = tid + it * 256;   // 0..511
            int l  = i >> 3;           // 8 float4 per row
            int c4 = i & 7;
            float4 v = *reinterpret_cast<const float4*>(
                bbase + (size_t)l * (H * N) + c4 * 4);
            *reinterpret_cast<float4*>(&Bs[l][c4 * 4]) = v;
        }
    }

    // ---- warp-shfl inclusive scan of A (overlaps the loads) ----
    if (tid < L) {
        float c = a;
        #pragma unroll
        for (int off = 1; off < 32; off <<= 1) {
            float t = __shfl_up_sync(0xffffffffu, c, off);
            if (lane >= off) c += t;
        }
        wpart[tid] = c;
        if (lane == 31) wtot[tid >> 5] = c;
    }
    __syncthreads();

    // ---- fold w into B rows, computing w[l] = exp(2S - cc[l]) inline ----
    {
        const float tot0 = wtot[0];
        const float twoS = 2.f * (tot0 + wtot[1]);
        #pragma unroll
        for (int it = 0; it < 2; it++) {
            int i   = tid + it * 256;
            int l   = i >> 3;
            int c4  = i & 7;
            float cc = wpart[l] + (l >= 32 ? tot0 : 0.f);
            float wl = __expf(twoS - cc);
            float4 v = *reinterpret_cast<float4*>(&Bs[l][c4 * 4]);
            v.x *= wl; v.y *= wl; v.z *= wl; v.w *= wl;
            *reinterpret_cast<float4*>(&Bs[l][c4 * 4]) = v;
        }
    }
    __syncthreads();

    // ---- compute: thread -> (p, 8 consecutive n) with packed f32x2 FMA ----
    const int p  = tid & 63;
    const int ng = tid >> 6;           // 0..3

    unsigned long long acc0 = 0ull, acc1 = 0ull, acc2 = 0ull, acc3 = 0ull;

    #pragma unroll
    for (int l = 0; l < L; l++) {
        float xv = Xs[l][p];                          // conflict-free LDS
        unsigned long long x2;
        asm("mov.b64 %0, {%1, %1};" : "=l"(x2) : "f"(xv));
        const ulonglong2* bp =
            reinterpret_cast<const ulonglong2*>(&Bs[l][ng * 8]);  // 32B aligned
        ulonglong2 q0 = bp[0];                        // LDS.128 broadcast
        ulonglong2 q1 = bp[1];                        // LDS.128 broadcast
        fma2(acc0, x2, q0.x);
        fma2(acc1, x2, q0.y);
        fma2(acc2, x2, q1.x);
        fma2(acc3, x2, q1.y);
    }

    float* o = out + ((size_t)(bh * P + p)) * N + ntile * 32 + ng * 8;
    ulonglong2 s0; s0.x = acc0; s0.y = acc1;
    ulonglong2 s1; s1.x = acc2; s1.y = acc3;
    *reinterpret_cast<ulonglong2*>(o)     = s0;       // STG.128
    *reinterpret_cast<ulonglong2*>(o + 4) = s1;       // STG.128
}

} // namespace

extern "C" void kernel_launch(void* const* d_in, const int* in_sizes, int n_in,
                              void* d_out, int out_size) {
    const float* X = (const float*)d_in[0];  // (2, 4096, 16, 64)  f32
    const float* A = (const float*)d_in[1];  // (2, 4096, 16)      f32
    const float* B = (const float*)d_in[2];  // (2, 4096, 16, 128) f32
    float* out = (float*)d_out;              // (2, 16, 64, 128)   f32

    dim3 grid(32, 4);   // (b*h pairs, n-tiles of 32)
    mamba_final_state_kernel<<<grid, 256>>>(X, A, B, out);
}

// round 16
// speedup vs baseline: 1.2947x; 1.2609x over previous
#include <cuda_runtime.h>

namespace {

constexpr int T  = 4096;
constexpr int H  = 16;
constexpr int P  = 64;    // d_head
constexpr int N  = 128;   // d_state
constexpr int L  = 64;    // block_len (last chunk)
constexpr int T0 = T - L; // 4032

__device__ __forceinline__ void fma2(unsigned long long& d,
                                     unsigned long long a,
                                     unsigned long long b) {
    asm("fma.rn.f32x2 %0, %1, %2, %0;" : "+l"(d) : "l"(a), "l"(b));
}

__global__ __launch_bounds__(128, 1)
void mamba_final_state_kernel(const float* __restrict__ X,
                              const float* __restrict__ A,
                              const float* __restrict__ Bm,
                              float* __restrict__ out) {
    const int bh    = blockIdx.x;      // 0..31  (b*16 + h)
    const int b     = bh >> 4;
    const int h     = bh & 15;
    const int ntile = blockIdx.y;      // 0..3, 32 n-columns each
    const int tid   = threadIdx.x;     // 128 threads

    const int lane  = tid & 31;

    __shared__ float Xs[L][P];         // 16 KB, raw X
    __shared__ float Bs[L][32];        // 8 KB, scaled by w[l] in fold pass
    __shared__ float wpart[L];         // inclusive-scan partials
    __shared__ float wtot[2];          // warp totals

    // ---- issue ALL gmem loads up front (no dependency between them) ----

    // A for last chunk -> registers of threads 0..63
    float a = 0.f;
    if (tid < L)
        a = A[(size_t)(b * T + T0 + tid) * H + h];

    // X tile raw: 64x64 = 1024 float4, 8 per thread
    {
        const float* xbase = X + (size_t)(b * T + T0) * (H * P) + (size_t)h * P;
        #pragma unroll
        for (int it = 0; it < 8; it++) {
            int i  = tid + it * 128;   // 0..1023
            int l  = i >> 4;           // 16 float4 per row
            int c4 = i & 15;
            float4 v = *reinterpret_cast<const float4*>(
                xbase + (size_t)l * (H * P) + c4 * 4);
            *reinterpret_cast<float4*>(&Xs[l][c4 * 4]) = v;
        }
    }

    // B tile raw: 64x32 = 512 float4, 4 per thread
    {
        const float* bbase = Bm + (size_t)(b * T + T0) * (H * N)
                                + (size_t)h * N + ntile * 32;
        #pragma unroll
        for (int it = 0; it < 4; it++) {
            int i  = tid + it * 128;   // 0..511
            int l  = i >> 3;           // 8 float4 per row
            int c4 = i & 7;
            float4 v = *reinterpret_cast<const float4*>(
                bbase + (size_t)l * (H * N) + c4 * 4);
            *reinterpret_cast<float4*>(&Bs[l][c4 * 4]) = v;
        }
    }

    // ---- warp-shfl inclusive scan of A (overlaps the loads) ----
    if (tid < L) {
        float c = a;
        #pragma unroll
        for (int off = 1; off < 32; off <<= 1) {
            float t = __shfl_up_sync(0xffffffffu, c, off);
            if (lane >= off) c += t;
        }
        wpart[tid] = c;
        if (lane == 31) wtot[tid >> 5] = c;
    }
    __syncthreads();

    // ---- fold w into B rows, computing w[l] = exp(2S - cc[l]) inline ----
    {
        const float tot0 = wtot[0];
        const float twoS = 2.f * (tot0 + wtot[1]);
        #pragma unroll
        for (int it = 0; it < 4; it++) {
            int i   = tid + it * 128;
            int l   = i >> 3;
            int c4  = i & 7;
            float cc = wpart[l] + (l >= 32 ? tot0 : 0.f);
            float wl = __expf(twoS - cc);
            float4 v = *reinterpret_cast<float4*>(&Bs[l][c4 * 4]);
            v.x *= wl; v.y *= wl; v.z *= wl; v.w *= wl;
            *reinterpret_cast<float4*>(&Bs[l][c4 * 4]) = v;
        }
    }
    __syncthreads();

    // ---- compute: thread -> (2 consecutive p, 8 consecutive n) ----
    const int p2 = (tid & 31) * 2;     // p, p+1
    const int ng = tid >> 5;           // 0..3 (8 n's)

    // accumulators: [p-offset][n-pair], packed f32x2 over n
    unsigned long long accA0 = 0ull, accA1 = 0ull, accA2 = 0ull, accA3 = 0ull;
    unsigned long long accB0 = 0ull, accB1 = 0ull, accB2 = 0ull, accB3 = 0ull;

    #pragma unroll
    for (int l = 0; l < L; l++) {
        float2 xv = *reinterpret_cast<const float2*>(&Xs[l][p2]);  // LDS.64
        unsigned long long xa, xb;
        asm("mov.b64 %0, {%1, %1};" : "=l"(xa) : "f"(xv.x));
        asm("mov.b64 %0, {%1, %1};" : "=l"(xb) : "f"(xv.y));
        const ulonglong2* bp =
            reinterpret_cast<const ulonglong2*>(&Bs[l][ng * 8]);   // 32B aligned
        ulonglong2 q0 = bp[0];                        // LDS.128 broadcast
        ulonglong2 q1 = bp[1];                        // LDS.128 broadcast
        fma2(accA0, xa, q0.x); fma2(accA1, xa, q0.y);
        fma2(accA2, xa, q1.x); fma2(accA3, xa, q1.y);
        fma2(accB0, xb, q0.x); fma2(accB1, xb, q0.y);
        fma2(accB2, xb, q1.x); fma2(accB3, xb, q1.y);
    }

    float* o0 = out + ((size_t)(bh * P + p2)) * N + ntile * 32 + ng * 8;
    float* o1 = o0 + N;
    ulonglong2 sA0; sA0.x = accA0; sA0.y = accA1;
    ulonglong2 sA1; sA1.x = accA2; sA1.y = accA3;
    ulonglong2 sB0; sB0.x = accB0; sB0.y = accB1;
    ulonglong2 sB1; sB1.x = accB2; sB1.y = accB3;
    *reinterpret_cast<ulonglong2*>(o0)     = sA0;     // STG.128
    *reinterpret_cast<ulonglong2*>(o0 + 4) = sA1;
    *reinterpret_cast<ulonglong2*>(o1)     = sB0;
    *reinterpret_cast<ulonglong2*>(o1 + 4) = sB1;
}

} // namespace

extern "C" void kernel_launch(void* const* d_in, const int* in_sizes, int n_in,
                              void* d_out, int out_size) {
    const float* X = (const float*)d_in[0];  // (2, 4096, 16, 64)  f32
    const float* A = (const float*)d_in[1];  // (2, 4096, 16)      f32
    const float* B = (const float*)d_in[2];  // (2, 4096, 16, 128) f32
    float* out = (float*)d_out;              // (2, 16, 64, 128)   f32

    dim3 grid(32, 4);   // (b*h pairs, n-tiles of 32)
    mamba_final_state_kernel<<<grid, 128>>>(X, A, B, out);
}